// round 15
// baseline (speedup 1.0000x reference)
#include <cuda_runtime.h>
#include <cuda_bf16.h>
#include <cstdint>

#define C_  512
#define Hh  24
#define Ww  24
#define HW  576
#define NH  8
#define HD  64
#define PW  30
#define PP  900
#define KP  960            /* keys produced by gemm */
#define KPA 1024           /* attn padded key count (8 chunks of 128) */
#define SEW 1028           /* sE row stride: 4 mod 32 -> conflict-free frag reads */
#define VST 140            /* V smem stride: 12 mod 32 -> conflict-free B-frags */

typedef unsigned long long ull;

// Scratch (device globals: allocation-free)
__device__ float g_Xp[C_ * KP];    // reflect-padded x
__device__ float g_QT[HW * C_];    // Q transposed: [p][o]
__device__ float g_KT[KPA * C_];   // K transposed: [pp][o]; rows 960..1023 zeroed
__device__ float g_V [C_ * KPA];   // V: [o][pp]; cols 960..1023 zeroed

// ---- tf32 helpers (attention) ----
__device__ __forceinline__ uint32_t f2tf(float f) {
    uint32_t r; asm("cvt.rna.tf32.f32 %0, %1;" : "=r"(r) : "f"(f)); return r;
}
__device__ __forceinline__ void mma_tf32(float* c, const uint32_t* a, const uint32_t* b) {
    asm("mma.sync.aligned.m16n8k8.row.col.f32.tf32.tf32.f32 "
        "{%0,%1,%2,%3}, {%4,%5,%6,%7}, {%8,%9}, {%0,%1,%2,%3};"
        : "+f"(c[0]), "+f"(c[1]), "+f"(c[2]), "+f"(c[3])
        : "r"(a[0]), "r"(a[1]), "r"(a[2]), "r"(a[3]), "r"(b[0]), "r"(b[1]));
}

// ---- bf16 helpers (gemm) ----
__device__ __forceinline__ uint32_t pkbf(float lo, float hi) {
    __nv_bfloat162 h = __floats2bfloat162_rn(lo, hi);
    return *(uint32_t*)&h;
}
__device__ __forceinline__ void mma_bf16(float* c, const uint32_t* a, const uint32_t* b) {
    asm("mma.sync.aligned.m16n8k16.row.col.f32.bf16.bf16.f32 "
        "{%0,%1,%2,%3}, {%4,%5,%6,%7}, {%8,%9}, {%0,%1,%2,%3};"
        : "+f"(c[0]), "+f"(c[1]), "+f"(c[2]), "+f"(c[3])
        : "r"(a[0]), "r"(a[1]), "r"(a[2]), "r"(a[3]), "r"(b[0]), "r"(b[1]));
}

// ---------------------------------------------------------------------------
// Kernel 1: reflect-pad gather + zero the attn key-pad regions.
// ---------------------------------------------------------------------------
__global__ void pad_kernel(const float* __restrict__ x) {
    int bid = blockIdx.x;
    if (bid < 1920) {
        int idx = bid * 256 + threadIdx.x;
        int c = idx / KP, pp = idx - c * KP;
        float v = 0.f;
        if (pp < PP) {
            int pr = pp / PW, pc = pp - pr * PW;
            int r = pr - 3; r = (r < 0) ? -r : ((r >= Hh) ? 2 * Hh - 2 - r : r);
            int cl = pc - 3; cl = (cl < 0) ? -cl : ((cl >= Ww) ? 2 * Ww - 2 - cl : cl);
            v = x[c * HW + r * Ww + cl];
        }
        g_Xp[idx] = v;
    } else {
        int i = (bid - 1920) * 256 + threadIdx.x;    // [0, 65536)
        if (i < 32768) {
            g_KT[KP * C_ + i] = 0.f;                 // K rows 960..1023
        } else {
            int j = i - 32768;
            int row = j >> 6, col = j & 63;
            g_V[row * KPA + KP + col] = 0.f;         // V cols 960..1023
        }
    }
}

// ---------------------------------------------------------------------------
// Kernel 2: three conv1x1 GEMMs via mma.sync BF16 m16n8k16 (R13 verbatim,
// except V output row stride = KPA).
// ---------------------------------------------------------------------------
__global__ void __launch_bounds__(128) gemm_all_kernel(
    const float* __restrict__ Wq, const float* __restrict__ bq,
    const float* __restrict__ Wk, const float* __restrict__ bk,
    const float* __restrict__ Wv, const float* __restrict__ bv,
    const float* __restrict__ x)
{
    __shared__ uint32_t smu[4736];
    uint32_t* sA[2] = { smu,        smu + 1280 };   // [o=64][k2], stride 20
    uint32_t* sB[2] = { smu + 2560, smu + 3648 };   // [k2=16][n], stride 68

    int bid = blockIdx.x;
    const float *Wm, *bias, *X; float* Cout; int N, Nst, transp, nt, ot;
    if (bid < 72)       { nt = bid % 9;      ot = bid / 9;       Wm = Wq; bias = bq; X = x;    Cout = g_QT; N = HW; Nst = HW;  transp = 1; }
    else if (bid < 192) { int b = bid - 72;  nt = b % 15; ot = b / 15; Wm = Wk; bias = bk; X = g_Xp; Cout = g_KT; N = KP; Nst = KP;  transp = 1; }
    else                { int b = bid - 192; nt = b % 15; ot = b / 15; Wm = Wv; bias = bv; X = g_Xp; Cout = g_V;  N = KP; Nst = KPA; transp = 0; }
    int nB = nt * 64, oB = ot * 64;

    int tid  = threadIdx.x;
    int lane = tid & 31, wid = tid >> 5;
    int warp_m = wid & 1, warp_n = wid >> 1;
    int grp = lane >> 2, qd = lane & 3;

    int arow = tid >> 1, ahalf = tid & 1;
    int bk2  = tid >> 3, bng = (tid & 7) << 3;

    float acc[2][4][4];
#pragma unroll
    for (int i = 0; i < 2; i++)
#pragma unroll
        for (int j = 0; j < 4; j++)
#pragma unroll
            for (int e = 0; e < 4; e++) acc[i][j][e] = 0.f;

    {
        const float4* aS = (const float4*)&Wm[(oB + arow) * C_ + ahalf * 16];
        const float4* b0S = (const float4*)&X[(2 * bk2    ) * N + nB + bng];
        const float4* b1S = (const float4*)&X[(2 * bk2 + 1) * N + nB + bng];
        uint32_t aw[8], bw[8];
#pragma unroll
        for (int g = 0; g < 4; g++) {
            float4 w = aS[g];
            aw[2 * g]     = pkbf(w.x, w.y);
            aw[2 * g + 1] = pkbf(w.z, w.w);
        }
#pragma unroll
        for (int g = 0; g < 2; g++) {
            float4 lo = b0S[g], hi = b1S[g];
            bw[4 * g + 0] = pkbf(lo.x, hi.x);
            bw[4 * g + 1] = pkbf(lo.y, hi.y);
            bw[4 * g + 2] = pkbf(lo.z, hi.z);
            bw[4 * g + 3] = pkbf(lo.w, hi.w);
        }
        *(uint4*)&sA[0][arow * 20 + ahalf * 8]     = *(uint4*)&aw[0];
        *(uint4*)&sA[0][arow * 20 + ahalf * 8 + 4] = *(uint4*)&aw[4];
        *(uint4*)&sB[0][bk2 * 68 + bng]            = *(uint4*)&bw[0];
        *(uint4*)&sB[0][bk2 * 68 + bng + 4]        = *(uint4*)&bw[4];
    }
    __syncthreads();

    int buf = 0;
    for (int cc = 0; cc < C_; cc += 32) {
        bool pf = cc + 32 < C_;
        float4 wreg[4], x0reg[2], x1reg[2];
        if (pf) {
            const float4* aS = (const float4*)&Wm[(oB + arow) * C_ + cc + 32 + ahalf * 16];
            const float4* b0S = (const float4*)&X[(cc + 32 + 2 * bk2    ) * N + nB + bng];
            const float4* b1S = (const float4*)&X[(cc + 32 + 2 * bk2 + 1) * N + nB + bng];
#pragma unroll
            for (int g = 0; g < 4; g++) wreg[g] = aS[g];
            x0reg[0] = b0S[0]; x0reg[1] = b0S[1];
            x1reg[0] = b1S[0]; x1reg[1] = b1S[1];
        }
        const uint32_t* cA = sA[buf];
        const uint32_t* cB = sB[buf];
#pragma unroll
        for (int ks = 0; ks < 2; ks++) {
            int kb = ks << 3;
            uint32_t afr[2][4];
#pragma unroll
            for (int ms = 0; ms < 2; ms++) {
                int base = warp_m * 32 + ms * 16 + grp;
                afr[ms][0] = cA[(base    ) * 20 + kb + qd];
                afr[ms][1] = cA[(base + 8) * 20 + kb + qd];
                afr[ms][2] = cA[(base    ) * 20 + kb + 4 + qd];
                afr[ms][3] = cA[(base + 8) * 20 + kb + 4 + qd];
            }
            uint32_t bfr[4][2];
#pragma unroll
            for (int ns = 0; ns < 4; ns++) {
                int n = warp_n * 32 + ns * 8 + grp;
                bfr[ns][0] = cB[(kb + qd    ) * 68 + n];
                bfr[ns][1] = cB[(kb + 4 + qd) * 68 + n];
            }
#pragma unroll
            for (int ms = 0; ms < 2; ms++)
#pragma unroll
                for (int ns = 0; ns < 4; ns++)
                    mma_bf16(acc[ms][ns], afr[ms], bfr[ns]);
        }
        if (pf) {
            uint32_t* nA = sA[buf ^ 1];
            uint32_t* nBp = sB[buf ^ 1];
            uint32_t aw[8], bw[8];
#pragma unroll
            for (int g = 0; g < 4; g++) {
                aw[2 * g]     = pkbf(wreg[g].x, wreg[g].y);
                aw[2 * g + 1] = pkbf(wreg[g].z, wreg[g].w);
            }
#pragma unroll
            for (int g = 0; g < 2; g++) {
                float4 lo = x0reg[g], hi = x1reg[g];
                bw[4 * g + 0] = pkbf(lo.x, hi.x);
                bw[4 * g + 1] = pkbf(lo.y, hi.y);
                bw[4 * g + 2] = pkbf(lo.z, hi.z);
                bw[4 * g + 3] = pkbf(lo.w, hi.w);
            }
            *(uint4*)&nA[arow * 20 + ahalf * 8]     = *(uint4*)&aw[0];
            *(uint4*)&nA[arow * 20 + ahalf * 8 + 4] = *(uint4*)&aw[4];
            *(uint4*)&nBp[bk2 * 68 + bng]           = *(uint4*)&bw[0];
            *(uint4*)&nBp[bk2 * 68 + bng + 4]       = *(uint4*)&bw[4];
        }
        __syncthreads();
        buf ^= 1;
    }

    if (!transp) {
#pragma unroll
        for (int ms = 0; ms < 2; ms++)
#pragma unroll
            for (int part = 0; part < 2; part++) {
                int row = warp_m * 32 + ms * 16 + grp + part * 8;
                float bv_ = bias[oB + row];
#pragma unroll
                for (int ns = 0; ns < 4; ns++) {
                    float2 val = make_float2(acc[ms][ns][2 * part] + bv_,
                                             acc[ms][ns][2 * part + 1] + bv_);
                    *(float2*)&Cout[(oB + row) * Nst + nB + warp_n * 32 + ns * 8 + 2 * qd] = val;
                }
            }
    } else {
        float* sT = (float*)smu;
        __syncthreads();
#pragma unroll
        for (int ms = 0; ms < 2; ms++)
#pragma unroll
            for (int part = 0; part < 2; part++) {
                int row = warp_m * 32 + ms * 16 + grp + part * 8;
                float bv_ = bias[oB + row];
#pragma unroll
                for (int ns = 0; ns < 4; ns++) {
                    int n = warp_n * 32 + ns * 8 + 2 * qd;
                    sT[(n    ) * 65 + row] = acc[ms][ns][2 * part] + bv_;
                    sT[(n + 1) * 65 + row] = acc[ms][ns][2 * part + 1] + bv_;
                }
            }
        __syncthreads();
#pragma unroll
        for (int it = 0; it < 32; it++) {
            int idx = it * 128 + tid;
            int n = idx >> 6, o = idx & 63;
            Cout[(nB + n) * C_ + oB + o] = sT[n * 65 + o];
        }
    }
}

// ---------------------------------------------------------------------------
// Kernel 3: fused attention via mma.sync tf32, 128-KEY CHUNKS (8 chunks).
// Grid (18, 8) = 144 CTAs x 256 thr; smem 211.6KB. Syncs: 30 -> 17.
// Pass-1: warp owns 16 keys/chunk (2 n-subtiles). Pass-2: 16 ks per chunk.
// ---------------------------------------------------------------------------
__global__ void __launch_bounds__(256) attn_kernel(const float* __restrict__ x,
                            const float* __restrict__ gamma_p,
                            float* __restrict__ out) {
    extern __shared__ float smd[];
    uint32_t* sQf = (uint32_t*)smd;        // 2048: A-frags [ms 2][ks 8][lane 32][4]
    float* sKV0 = smd + 2048;              // 8960 (K: [128][68] / V: [64][140])
    float* sKV1 = sKV0 + 8960;             // 8960
    float* sE   = sKV1 + 8960;             // 32*1028 = 32896
    float* sInv = sE + 32 * SEW;           // 32

    int h   = blockIdx.y;
    int q0  = blockIdx.x * 32;
    int tid = threadIdx.x;
    int w = tid >> 5, lane = tid & 31, grp = lane >> 2, qd = lane & 3;
    int kd = tid >> 1, kg = (tid & 1) << 5;      // K staging: row, 32-float half
    int vd = tid >> 2, vg = (tid & 3) << 5;      // V staging: d-row, 32-float group
    float* sKVb[2] = { sKV0, sKV1 };

    // ---- Stage Q fragments (one-time) ----
    {
        int q = tid >> 3, db = (tid & 7) << 3;
        float4 qa = *(const float4*)&g_QT[(q0 + q) * C_ + h * HD + db];
        float4 qb = *(const float4*)&g_QT[(q0 + q) * C_ + h * HD + db + 4];
        int ms = q >> 4, qg = q & 7, hi = (q >> 3) & 1;
        float qv[8] = {qa.x, qa.y, qa.z, qa.w, qb.x, qb.y, qb.z, qb.w};
#pragma unroll
        for (int e = 0; e < 8; e++) {
            int d = db + e;
            sQf[((ms * 8 + (d >> 3)) * 32 + (qg << 2) + (d & 3)) * 4 + hi + (((d >> 2) & 1) << 1)] = f2tf(qv[e]);
        }
    }
    // ---- preload K chunk 0: sK[key][68], 128 keys ----
    {
        const float4* src = (const float4*)&g_KT[kd * C_ + h * HD + kg];
        uint32_t* dst = (uint32_t*)&sKV0[kd * 68 + kg];
#pragma unroll
        for (int j = 0; j < 8; j++) {
            float4 r = src[j];
            *(uint4*)&dst[4 * j] = make_uint4(f2tf(r.x), f2tf(r.y), f2tf(r.z), f2tf(r.w));
        }
    }
    __syncthreads();

    // ---- Pass 1: E = Q^T K, 8 chunks of 128 keys ----
    for (int kc = 0, c = 0; kc < KPA; kc += 128, c++) {
        const uint32_t* cK = (const uint32_t*)sKVb[c & 1];
        bool pf = kc + 128 < KPA;
        float4 r[8];
        if (pf) {
            const float4* src = (const float4*)&g_KT[(kc + 128 + kd) * C_ + h * HD + kg];
#pragma unroll
            for (int j = 0; j < 8; j++) r[j] = src[j];
        }
        float acc[2][2][4];
#pragma unroll
        for (int i = 0; i < 2; i++)
#pragma unroll
            for (int j = 0; j < 2; j++)
#pragma unroll
                for (int e = 0; e < 4; e++) acc[i][j][e] = 0.f;
#pragma unroll
        for (int ks = 0; ks < 8; ks++) {
            uint4 a0 = *(const uint4*)&sQf[((    ks) * 32 + lane) * 4];
            uint4 a1 = *(const uint4*)&sQf[((8 + ks) * 32 + lane) * 4];
#pragma unroll
            for (int kn = 0; kn < 2; kn++) {
                int krow = w * 16 + kn * 8 + grp;
                uint32_t bf[2];
                bf[0] = cK[krow * 68 + ks * 8 + qd];
                bf[1] = cK[krow * 68 + ks * 8 + 4 + qd];
                mma_tf32(acc[0][kn], (const uint32_t*)&a0, bf);
                mma_tf32(acc[1][kn], (const uint32_t*)&a1, bf);
            }
        }
#pragma unroll
        for (int kn = 0; kn < 2; kn++) {
            int col = kc + w * 16 + kn * 8 + 2 * qd;
            *(float2*)&sE[(grp     ) * SEW + col] = make_float2(acc[0][kn][0], acc[0][kn][1]);
            *(float2*)&sE[(grp +  8) * SEW + col] = make_float2(acc[0][kn][2], acc[0][kn][3]);
            *(float2*)&sE[(grp + 16) * SEW + col] = make_float2(acc[1][kn][0], acc[1][kn][1]);
            *(float2*)&sE[(grp + 24) * SEW + col] = make_float2(acc[1][kn][2], acc[1][kn][3]);
        }
        if (pf) {
            uint32_t* dst = (uint32_t*)&sKVb[(c & 1) ^ 1][kd * 68 + kg];
#pragma unroll
            for (int j = 0; j < 8; j++)
                *(uint4*)&dst[4 * j] = make_uint4(f2tf(r[j].x), f2tf(r[j].y), f2tf(r[j].z), f2tf(r[j].w));
        }
        __syncthreads();
    }

    // ---- prefetch V chunk 0 (completes under softmax): sV[d][140] ----
    float4 vr[8];
    {
        const float4* src = (const float4*)&g_V[(h * HD + vd) * KPA + vg];
#pragma unroll
        for (int j = 0; j < 8; j++) vr[j] = src[j];
    }

    // ---- Multiplicity-weighted softmax over 1024 cols (pads: E=0, w=0) ----
    {
        int row = tid >> 3, part = tid & 7;
        float* Er = &sE[row * SEW];
        int i0 = part << 7;                      // 128 elems each
        float m = -1e30f;
        for (int i = i0; i < i0 + 128; i++) m = fmaxf(m, Er[i]);
        m = fmaxf(m, __shfl_xor_sync(~0u, m, 1));
        m = fmaxf(m, __shfl_xor_sync(~0u, m, 2));
        m = fmaxf(m, __shfl_xor_sync(~0u, m, 4));
        float s = 0.f;
        for (int i = i0; i < i0 + 128; i++) {
            float wgt = 0.f;
            if (i < PP) {
                int pr = i / PW, pc = i - pr * PW;
                int mr = min(pr + 1, min(7, PW - pr));
                int mc = min(pc + 1, min(7, PW - pc));
                wgt = (float)(mr * mc);
            }
            float p = __uint_as_float(f2tf(wgt * __expf(Er[i] - m)));
            Er[i] = p;
            s += p;
        }
        s += __shfl_xor_sync(~0u, s, 1);
        s += __shfl_xor_sync(~0u, s, 2);
        s += __shfl_xor_sync(~0u, s, 4);
        if (part == 0) sInv[row] = 1.f / s;
    }
    // store V chunk 0 into sKV0 (pass-1 done with it)
    {
        uint32_t* dst = (uint32_t*)&sKV0[vd * VST + vg];
#pragma unroll
        for (int j = 0; j < 8; j++)
            *(uint4*)&dst[4 * j] = make_uint4(f2tf(vr[j].x), f2tf(vr[j].y), f2tf(vr[j].z), f2tf(vr[j].w));
    }
    __syncthreads();

    // ---- Pass 2: out = P V, 8 chunks of 128 keys ----
    float o0[4] = {0.f, 0.f, 0.f, 0.f};
    float o1[4] = {0.f, 0.f, 0.f, 0.f};
    for (int kc = 0, c = 0; kc < KPA; kc += 128, c++) {
        const uint32_t* cV = (const uint32_t*)sKVb[c & 1];
        bool pf = kc + 128 < KPA;
        if (pf) {
            const float4* src = (const float4*)&g_V[(h * HD + vd) * KPA + kc + 128 + vg];
#pragma unroll
            for (int j = 0; j < 8; j++) vr[j] = src[j];
        }
#pragma unroll
        for (int ks = 0; ks < 16; ks++) {
            int colb = kc + ks * 8;
            uint32_t a0[4], a1[4], bf[2];
            a0[0] = __float_as_uint(sE[(grp     ) * SEW + colb + qd]);
            a0[1] = __float_as_uint(sE[(grp +  8) * SEW + colb + qd]);
            a0[2] = __float_as_uint(sE[(grp     ) * SEW + colb + 4 + qd]);
            a0[3] = __float_as_uint(sE[(grp +  8) * SEW + colb + 4 + qd]);
            a1[0] = __float_as_uint(sE[(grp + 16) * SEW + colb + qd]);
            a1[1] = __float_as_uint(sE[(grp + 24) * SEW + colb + qd]);
            a1[2] = __float_as_uint(sE[(grp + 16) * SEW + colb + 4 + qd]);
            a1[3] = __float_as_uint(sE[(grp + 24) * SEW + colb + 4 + qd]);
            bf[0] = cV[(w * 8 + grp) * VST + ks * 8 + qd];
            bf[1] = cV[(w * 8 + grp) * VST + ks * 8 + 4 + qd];
            mma_tf32(o0, a0, bf);
            mma_tf32(o1, a1, bf);
        }
        if (pf) {
            uint32_t* dst = (uint32_t*)&sKVb[(c & 1) ^ 1][vd * VST + vg];
#pragma unroll
            for (int j = 0; j < 8; j++)
                *(uint4*)&dst[4 * j] = make_uint4(f2tf(vr[j].x), f2tf(vr[j].y), f2tf(vr[j].z), f2tf(vr[j].w));
        }
        __syncthreads();
    }

    // ---- Epilogue via smem transpose: out = gamma*acc/denom + x ----
    {
        float* sT = sKV0;                        // [d][q] 64 x 33 = 2112
        int dc = w * 8 + 2 * qd;
        sT[(dc    ) * 33 + grp     ] = o0[0];
        sT[(dc + 1) * 33 + grp     ] = o0[1];
        sT[(dc    ) * 33 + grp +  8] = o0[2];
        sT[(dc + 1) * 33 + grp +  8] = o0[3];
        sT[(dc    ) * 33 + grp + 16] = o1[0];
        sT[(dc + 1) * 33 + grp + 16] = o1[1];
        sT[(dc    ) * 33 + grp + 24] = o1[2];
        sT[(dc + 1) * 33 + grp + 24] = o1[3];
        __syncthreads();
        float g = *gamma_p;
        for (int i = tid; i < 64 * 32; i += 256) {
            int d = i >> 5, q = i & 31;
            int gi = (h * HD + d) * HW + q0 + q;
            out[gi] = g * sT[d * 33 + q] * sInv[q] + x[gi];
        }
    }
}

// ---------------------------------------------------------------------------
extern "C" void kernel_launch(void* const* d_in, const int* in_sizes, int n_in,
                              void* d_out, int out_size) {
    const float* x     = (const float*)d_in[0];
    const float* Wq    = (const float*)d_in[1];
    const float* bq    = (const float*)d_in[2];
    const float* Wk    = (const float*)d_in[3];
    const float* bk    = (const float*)d_in[4];
    const float* Wv    = (const float*)d_in[5];
    const float* bv    = (const float*)d_in[6];
    const float* gamma = (const float*)d_in[7];
    float* out = (float*)d_out;

    pad_kernel<<<2176, 256>>>(x);
    gemm_all_kernel<<<312, 128>>>(Wq, bq, Wk, bk, Wv, bv, x);

    const int attn_smem = (2048 + 2 * 8960 + 32 * SEW + 32) * 4;  // 211584
    cudaFuncSetAttribute(attn_kernel, cudaFuncAttributeMaxDynamicSharedMemorySize, attn_smem);
    attn_kernel<<<dim3(HW / 32, NH), 256, attn_smem>>>(x, gamma, out);
}

// round 16
// speedup vs baseline: 1.4919x; 1.4919x over previous
#include <cuda_runtime.h>
#include <cuda_bf16.h>
#include <cstdint>

#define C_  512
#define Hh  24
#define Ww  24
#define HW  576
#define NH  8
#define HD  64
#define PW  30
#define PP  900
#define KP  960
#define SEW 964            /* sE row stride: 4 mod 32 */

typedef unsigned long long ull;

// Scratch (device globals: allocation-free)
__device__ float g_Xp[C_ * KP];   // reflect-padded x
__device__ float g_QT[HW * C_];   // Q transposed: [p][o]
__device__ float g_KT[KP * C_];   // K transposed: [pp][o]
__device__ float g_V [C_ * KP];   // V: [o][pp]

// ---- bf16 helpers ----
__device__ __forceinline__ uint32_t pkbf(float lo, float hi) {
    __nv_bfloat162 h = __floats2bfloat162_rn(lo, hi);
    return *(uint32_t*)&h;
}
__device__ __forceinline__ void mma_bf16(float* c, const uint32_t* a, const uint32_t* b) {
    asm("mma.sync.aligned.m16n8k16.row.col.f32.bf16.bf16.f32 "
        "{%0,%1,%2,%3}, {%4,%5,%6,%7}, {%8,%9}, {%0,%1,%2,%3};"
        : "+f"(c[0]), "+f"(c[1]), "+f"(c[2]), "+f"(c[3])
        : "r"(a[0]), "r"(a[1]), "r"(a[2]), "r"(a[3]), "r"(b[0]), "r"(b[1]));
}

// ---------------------------------------------------------------------------
// Kernel 1: reflect-pad gather (R13 verbatim).
// ---------------------------------------------------------------------------
__global__ void pad_kernel(const float* __restrict__ x) {
    int idx = blockIdx.x * 256 + threadIdx.x;
    if (idx >= C_ * KP) return;
    int c = idx / KP, pp = idx - c * KP;
    float v = 0.f;
    if (pp < PP) {
        int pr = pp / PW, pc = pp - pr * PW;
        int r = pr - 3; r = (r < 0) ? -r : ((r >= Hh) ? 2 * Hh - 2 - r : r);
        int cl = pc - 3; cl = (cl < 0) ? -cl : ((cl >= Ww) ? 2 * Ww - 2 - cl : cl);
        v = x[c * HW + r * Ww + cl];
    }
    g_Xp[idx] = v;
}

// ---------------------------------------------------------------------------
// Kernel 2: three conv1x1 GEMMs via mma.sync BF16 m16n8k16 (R13 verbatim).
// ---------------------------------------------------------------------------
__global__ void __launch_bounds__(128) gemm_all_kernel(
    const float* __restrict__ Wq, const float* __restrict__ bq,
    const float* __restrict__ Wk, const float* __restrict__ bk,
    const float* __restrict__ Wv, const float* __restrict__ bv,
    const float* __restrict__ x)
{
    __shared__ uint32_t smu[4736];
    uint32_t* sA[2] = { smu,        smu + 1280 };   // [o=64][k2], stride 20
    uint32_t* sB[2] = { smu + 2560, smu + 3648 };   // [k2=16][n], stride 68

    int bid = blockIdx.x;
    const float *Wm, *bias, *X; float* Cout; int N, transp, nt, ot;
    if (bid < 72)       { nt = bid % 9;      ot = bid / 9;       Wm = Wq; bias = bq; X = x;    Cout = g_QT; N = HW; transp = 1; }
    else if (bid < 192) { int b = bid - 72;  nt = b % 15; ot = b / 15; Wm = Wk; bias = bk; X = g_Xp; Cout = g_KT; N = KP; transp = 1; }
    else                { int b = bid - 192; nt = b % 15; ot = b / 15; Wm = Wv; bias = bv; X = g_Xp; Cout = g_V;  N = KP; transp = 0; }
    int nB = nt * 64, oB = ot * 64;

    int tid  = threadIdx.x;
    int lane = tid & 31, wid = tid >> 5;
    int warp_m = wid & 1, warp_n = wid >> 1;
    int grp = lane >> 2, qd = lane & 3;

    int arow = tid >> 1, ahalf = tid & 1;
    int bk2  = tid >> 3, bng = (tid & 7) << 3;

    float acc[2][4][4];
#pragma unroll
    for (int i = 0; i < 2; i++)
#pragma unroll
        for (int j = 0; j < 4; j++)
#pragma unroll
            for (int e = 0; e < 4; e++) acc[i][j][e] = 0.f;

    {
        const float4* aS = (const float4*)&Wm[(oB + arow) * C_ + ahalf * 16];
        const float4* b0S = (const float4*)&X[(2 * bk2    ) * N + nB + bng];
        const float4* b1S = (const float4*)&X[(2 * bk2 + 1) * N + nB + bng];
        uint32_t aw[8], bw[8];
#pragma unroll
        for (int g = 0; g < 4; g++) {
            float4 w = aS[g];
            aw[2 * g]     = pkbf(w.x, w.y);
            aw[2 * g + 1] = pkbf(w.z, w.w);
        }
#pragma unroll
        for (int g = 0; g < 2; g++) {
            float4 lo = b0S[g], hi = b1S[g];
            bw[4 * g + 0] = pkbf(lo.x, hi.x);
            bw[4 * g + 1] = pkbf(lo.y, hi.y);
            bw[4 * g + 2] = pkbf(lo.z, hi.z);
            bw[4 * g + 3] = pkbf(lo.w, hi.w);
        }
        *(uint4*)&sA[0][arow * 20 + ahalf * 8]     = *(uint4*)&aw[0];
        *(uint4*)&sA[0][arow * 20 + ahalf * 8 + 4] = *(uint4*)&aw[4];
        *(uint4*)&sB[0][bk2 * 68 + bng]            = *(uint4*)&bw[0];
        *(uint4*)&sB[0][bk2 * 68 + bng + 4]        = *(uint4*)&bw[4];
    }
    __syncthreads();

    int buf = 0;
    for (int cc = 0; cc < C_; cc += 32) {
        bool pf = cc + 32 < C_;
        float4 wreg[4], x0reg[2], x1reg[2];
        if (pf) {
            const float4* aS = (const float4*)&Wm[(oB + arow) * C_ + cc + 32 + ahalf * 16];
            const float4* b0S = (const float4*)&X[(cc + 32 + 2 * bk2    ) * N + nB + bng];
            const float4* b1S = (const float4*)&X[(cc + 32 + 2 * bk2 + 1) * N + nB + bng];
#pragma unroll
            for (int g = 0; g < 4; g++) wreg[g] = aS[g];
            x0reg[0] = b0S[0]; x0reg[1] = b0S[1];
            x1reg[0] = b1S[0]; x1reg[1] = b1S[1];
        }
        const uint32_t* cA = sA[buf];
        const uint32_t* cB = sB[buf];
#pragma unroll
        for (int ks = 0; ks < 2; ks++) {
            int kb = ks << 3;
            uint32_t afr[2][4];
#pragma unroll
            for (int ms = 0; ms < 2; ms++) {
                int base = warp_m * 32 + ms * 16 + grp;
                afr[ms][0] = cA[(base    ) * 20 + kb + qd];
                afr[ms][1] = cA[(base + 8) * 20 + kb + qd];
                afr[ms][2] = cA[(base    ) * 20 + kb + 4 + qd];
                afr[ms][3] = cA[(base + 8) * 20 + kb + 4 + qd];
            }
            uint32_t bfr[4][2];
#pragma unroll
            for (int ns = 0; ns < 4; ns++) {
                int n = warp_n * 32 + ns * 8 + grp;
                bfr[ns][0] = cB[(kb + qd    ) * 68 + n];
                bfr[ns][1] = cB[(kb + 4 + qd) * 68 + n];
            }
#pragma unroll
            for (int ms = 0; ms < 2; ms++)
#pragma unroll
                for (int ns = 0; ns < 4; ns++)
                    mma_bf16(acc[ms][ns], afr[ms], bfr[ns]);
        }
        if (pf) {
            uint32_t* nA = sA[buf ^ 1];
            uint32_t* nBp = sB[buf ^ 1];
            uint32_t aw[8], bw[8];
#pragma unroll
            for (int g = 0; g < 4; g++) {
                aw[2 * g]     = pkbf(wreg[g].x, wreg[g].y);
                aw[2 * g + 1] = pkbf(wreg[g].z, wreg[g].w);
            }
#pragma unroll
            for (int g = 0; g < 2; g++) {
                float4 lo = x0reg[g], hi = x1reg[g];
                bw[4 * g + 0] = pkbf(lo.x, hi.x);
                bw[4 * g + 1] = pkbf(lo.y, hi.y);
                bw[4 * g + 2] = pkbf(lo.z, hi.z);
                bw[4 * g + 3] = pkbf(lo.w, hi.w);
            }
            *(uint4*)&nA[arow * 20 + ahalf * 8]     = *(uint4*)&aw[0];
            *(uint4*)&nA[arow * 20 + ahalf * 8 + 4] = *(uint4*)&aw[4];
            *(uint4*)&nBp[bk2 * 68 + bng]           = *(uint4*)&bw[0];
            *(uint4*)&nBp[bk2 * 68 + bng + 4]       = *(uint4*)&bw[4];
        }
        __syncthreads();
        buf ^= 1;
    }

    if (!transp) {
#pragma unroll
        for (int ms = 0; ms < 2; ms++)
#pragma unroll
            for (int part = 0; part < 2; part++) {
                int row = warp_m * 32 + ms * 16 + grp + part * 8;
                float bv_ = bias[oB + row];
#pragma unroll
                for (int ns = 0; ns < 4; ns++) {
                    float2 val = make_float2(acc[ms][ns][2 * part] + bv_,
                                             acc[ms][ns][2 * part + 1] + bv_);
                    *(float2*)&Cout[(oB + row) * N + nB + warp_n * 32 + ns * 8 + 2 * qd] = val;
                }
            }
    } else {
        float* sT = (float*)smu;
        __syncthreads();
#pragma unroll
        for (int ms = 0; ms < 2; ms++)
#pragma unroll
            for (int part = 0; part < 2; part++) {
                int row = warp_m * 32 + ms * 16 + grp + part * 8;
                float bv_ = bias[oB + row];
#pragma unroll
                for (int ns = 0; ns < 4; ns++) {
                    int n = warp_n * 32 + ns * 8 + 2 * qd;
                    sT[(n    ) * 65 + row] = acc[ms][ns][2 * part] + bv_;
                    sT[(n + 1) * 65 + row] = acc[ms][ns][2 * part + 1] + bv_;
                }
            }
        __syncthreads();
#pragma unroll
        for (int it = 0; it < 32; it++) {
            int idx = it * 128 + tid;
            int n = idx >> 6, o = idx & 63;
            Cout[(nB + n) * C_ + oB + o] = sT[n * 65 + o];
        }
    }
}

// ---------------------------------------------------------------------------
// Kernel 3: fused attention, ALL-BF16 mma m16n8k16.
// Grid (18,8) = 144 CTAs x 256 thr. smem 146KB.
// K smem [key][d-pair] stride 36; V smem [d][key-pair] stride 36.
// P packed bf16 in place during softmax, slot(j)=2j+((j&3)>>1) (conflict-free).
// ---------------------------------------------------------------------------
__global__ void __launch_bounds__(256) attn_kernel(const float* __restrict__ x,
                            const float* __restrict__ gamma_p,
                            float* __restrict__ out) {
    extern __shared__ float smd[];
    uint32_t* sQf = (uint32_t*)smd;        // 1024 u32: [ms2][ks4][lane32][4]
    uint32_t* sKV0 = (uint32_t*)(smd + 1024);   // 64*36 = 2304 u32
    uint32_t* sKV1 = sKV0 + 2304;               // 2304
    float* sE   = smd + 1024 + 4608;       // 32*964 = 30848
    float* sInv = sE + 32 * SEW;           // 32

    int h   = blockIdx.y;
    int q0  = blockIdx.x * 32;
    int tid = threadIdx.x;
    int w = tid >> 5, lane = tid & 31, grp = lane >> 2, qd = lane & 3;
    int kd = tid >> 2, kg = (tid & 3) << 4;      // staging: row, 16-float group
    uint32_t* sKVb[2] = { sKV0, sKV1 };

    // ---- Stage Q fragments (one-time), bf16 pairs along d ----
    {
        int q = tid >> 3, db = (tid & 7) << 3;
        float4 qa = *(const float4*)&g_QT[(q0 + q) * C_ + h * HD + db];
        float4 qb = *(const float4*)&g_QT[(q0 + q) * C_ + h * HD + db + 4];
        float qv[8] = {qa.x, qa.y, qa.z, qa.w, qb.x, qb.y, qb.z, qb.w};
        int ms = q >> 4, qrow = q & 15;
        int reg = (((db >> 3) & 1) << 1) + (qrow >> 3);
        int base = ((ms * 4 + (db >> 4)) * 32 + (qrow & 7) * 4) * 4 + reg;
#pragma unroll
        for (int j = 0; j < 4; j++)
            sQf[base + j * 4] = pkbf(qv[2 * j], qv[2 * j + 1]);
    }
    // ---- preload K chunk 0: sK[key][36], pairs along d ----
    {
        const float4* src = (const float4*)&g_KT[kd * C_ + h * HD + kg];
        uint32_t pw[8];
#pragma unroll
        for (int j = 0; j < 4; j++) {
            float4 r = src[j];
            pw[2 * j]     = pkbf(r.x, r.y);
            pw[2 * j + 1] = pkbf(r.z, r.w);
        }
        *(uint4*)&sKV0[kd * 36 + (kg >> 1)]     = *(uint4*)&pw[0];
        *(uint4*)&sKV0[kd * 36 + (kg >> 1) + 4] = *(uint4*)&pw[4];
    }
    __syncthreads();

    // ---- Pass 1: E = Q^T K, 15 chunks of 64 keys, bf16 k16 ----
    for (int kc = 0, c = 0; kc < KP; kc += 64, c++) {
        const uint32_t* cK = sKVb[c & 1];
        bool pf = kc + 64 < KP;
        float4 r0, r1, r2, r3;
        if (pf) {
            const float4* src = (const float4*)&g_KT[(kc + 64 + kd) * C_ + h * HD + kg];
            r0 = src[0]; r1 = src[1]; r2 = src[2]; r3 = src[3];
        }
        float acc0[4] = {0.f, 0.f, 0.f, 0.f};
        float acc1[4] = {0.f, 0.f, 0.f, 0.f};
#pragma unroll
        for (int ks = 0; ks < 4; ks++) {
            uint4 a0 = *(const uint4*)&sQf[((    ks) * 32 + lane) * 4];
            uint4 a1 = *(const uint4*)&sQf[((4 + ks) * 32 + lane) * 4];
            uint32_t bf[2];
            bf[0] = cK[(w * 8 + grp) * 36 + ks * 8 + qd];
            bf[1] = cK[(w * 8 + grp) * 36 + ks * 8 + 4 + qd];
            mma_bf16(acc0, (const uint32_t*)&a0, bf);
            mma_bf16(acc1, (const uint32_t*)&a1, bf);
        }
        {
            int col = kc + w * 8 + 2 * qd;
            *(float2*)&sE[(grp     ) * SEW + col] = make_float2(acc0[0], acc0[1]);
            *(float2*)&sE[(grp +  8) * SEW + col] = make_float2(acc0[2], acc0[3]);
            *(float2*)&sE[(grp + 16) * SEW + col] = make_float2(acc1[0], acc1[1]);
            *(float2*)&sE[(grp + 24) * SEW + col] = make_float2(acc1[2], acc1[3]);
        }
        if (pf) {
            uint32_t pw[8];
            pw[0] = pkbf(r0.x, r0.y); pw[1] = pkbf(r0.z, r0.w);
            pw[2] = pkbf(r1.x, r1.y); pw[3] = pkbf(r1.z, r1.w);
            pw[4] = pkbf(r2.x, r2.y); pw[5] = pkbf(r2.z, r2.w);
            pw[6] = pkbf(r3.x, r3.y); pw[7] = pkbf(r3.z, r3.w);
            uint32_t* dst = &sKVb[(c & 1) ^ 1][kd * 36 + (kg >> 1)];
            *(uint4*)&dst[0] = *(uint4*)&pw[0];
            *(uint4*)&dst[4] = *(uint4*)&pw[4];
        }
        __syncthreads();
    }

    // ---- prefetch V chunk 0 (keys 0..63 of all 64 d) ----
    float4 v0r, v1r, v2r, v3r;
    {
        const float4* src = (const float4*)&g_V[(h * HD + kd) * KP + kg];
        v0r = src[0]; v1r = src[1]; v2r = src[2]; v3r = src[3];
    }

    // ---- Weighted softmax; P -> bf16 pairs in place, slot(j)=2j+((j&3)>>1) ----
    {
        int row = tid >> 3, part = tid & 7;
        float* Er = &sE[row * SEW];
        uint32_t* Eu = (uint32_t*)Er;
        int i0 = part * 120;
        float m = -1e30f;
        for (int i = i0; i < i0 + 120; i++) m = fmaxf(m, Er[i]);
        m = fmaxf(m, __shfl_xor_sync(~0u, m, 1));
        m = fmaxf(m, __shfl_xor_sync(~0u, m, 2));
        m = fmaxf(m, __shfl_xor_sync(~0u, m, 4));
        float s = 0.f;
        for (int i = i0; i < i0 + 120; i += 2) {
            float e0 = Er[i], e1 = Er[i + 1];
            float w0 = 0.f, w1 = 0.f;
            {
                int pr = i / PW, pc = i - pr * PW;
                int mr = min(pr + 1, min(7, PW - pr));
                int mc = min(pc + 1, min(7, PW - pc));
                w0 = (float)(mr * mc);
            }
            {
                int i1 = i + 1;
                int pr = i1 / PW, pc = i1 - pr * PW;
                int mr = min(pr + 1, min(7, PW - pr));
                int mc = min(pc + 1, min(7, PW - pc));
                w1 = (float)(mr * mc);
            }
            float p0 = w0 * __expf(e0 - m);
            float p1 = w1 * __expf(e1 - m);
            __nv_bfloat162 h2 = __floats2bfloat162_rn(p0, p1);
            s += __bfloat162float(h2.x) + __bfloat162float(h2.y);
            int j = i >> 1;
            Eu[2 * j + ((j & 3) >> 1)] = *(uint32_t*)&h2;
        }
        s += __shfl_xor_sync(~0u, s, 1);
        s += __shfl_xor_sync(~0u, s, 2);
        s += __shfl_xor_sync(~0u, s, 4);
        if (part == 0) sInv[row] = 1.f / s;
    }
    // store V chunk 0: sV[d][36], pairs along key
    {
        uint32_t pw[8];
        pw[0] = pkbf(v0r.x, v0r.y); pw[1] = pkbf(v0r.z, v0r.w);
        pw[2] = pkbf(v1r.x, v1r.y); pw[3] = pkbf(v1r.z, v1r.w);
        pw[4] = pkbf(v2r.x, v2r.y); pw[5] = pkbf(v2r.z, v2r.w);
        pw[6] = pkbf(v3r.x, v3r.y); pw[7] = pkbf(v3r.z, v3r.w);
        uint32_t* dst = &sKV0[kd * 36 + (kg >> 1)];
        *(uint4*)&dst[0] = *(uint4*)&pw[0];
        *(uint4*)&dst[4] = *(uint4*)&pw[4];
    }
    __syncthreads();

    // ---- Pass 2: out = P V, bf16 k16, 15 chunks of 64 keys ----
    float o0[4] = {0.f, 0.f, 0.f, 0.f};
    float o1[4] = {0.f, 0.f, 0.f, 0.f};
    const uint32_t* sEp = (const uint32_t*)sE;
    int qoff = 2 * qd + (qd >> 1);
    for (int kc = 0, c = 0; kc < KP; kc += 64, c++) {
        const uint32_t* cV = sKVb[c & 1];
        bool pf = kc + 64 < KP;
        float4 r0, r1, r2, r3;
        if (pf) {
            const float4* src = (const float4*)&g_V[(h * HD + kd) * KP + kc + 64 + kg];
            r0 = src[0]; r1 = src[1]; r2 = src[2]; r3 = src[3];
        }
#pragma unroll
        for (int ks = 0; ks < 4; ks++) {
            int cb = kc + 16 * ks;
            uint32_t a0[4], a1[4], bf[2];
            a0[0] = sEp[(grp     ) * SEW + cb + qoff];
            a0[1] = sEp[(grp +  8) * SEW + cb + qoff];
            a0[2] = sEp[(grp     ) * SEW + cb + 8 + qoff];
            a0[3] = sEp[(grp +  8) * SEW + cb + 8 + qoff];
            a1[0] = sEp[(grp + 16) * SEW + cb + qoff];
            a1[1] = sEp[(grp + 24) * SEW + cb + qoff];
            a1[2] = sEp[(grp + 16) * SEW + cb + 8 + qoff];
            a1[3] = sEp[(grp + 24) * SEW + cb + 8 + qoff];
            bf[0] = cV[(w * 8 + grp) * 36 + ks * 8 + qd];
            bf[1] = cV[(w * 8 + grp) * 36 + ks * 8 + 4 + qd];
            mma_bf16(o0, a0, bf);
            mma_bf16(o1, a1, bf);
        }
        if (pf) {
            uint32_t pw[8];
            pw[0] = pkbf(r0.x, r0.y); pw[1] = pkbf(r0.z, r0.w);
            pw[2] = pkbf(r1.x, r1.y); pw[3] = pkbf(r1.z, r1.w);
            pw[4] = pkbf(r2.x, r2.y); pw[5] = pkbf(r2.z, r2.w);
            pw[6] = pkbf(r3.x, r3.y); pw[7] = pkbf(r3.z, r3.w);
            uint32_t* dst = &sKVb[(c & 1) ^ 1][kd * 36 + (kg >> 1)];
            *(uint4*)&dst[0] = *(uint4*)&pw[0];
            *(uint4*)&dst[4] = *(uint4*)&pw[4];
        }
        __syncthreads();
    }

    // ---- Epilogue via smem transpose: out = gamma*acc/denom + x ----
    {
        float* sT = (float*)sKV0;                // [d][q] 64 x 33 = 2112 <= 4608
        int dc = w * 8 + 2 * qd;
        sT[(dc    ) * 33 + grp     ] = o0[0];
        sT[(dc + 1) * 33 + grp     ] = o0[1];
        sT[(dc    ) * 33 + grp +  8] = o0[2];
        sT[(dc + 1) * 33 + grp +  8] = o0[3];
        sT[(dc    ) * 33 + grp + 16] = o1[0];
        sT[(dc + 1) * 33 + grp + 16] = o1[1];
        sT[(dc    ) * 33 + grp + 24] = o1[2];
        sT[(dc + 1) * 33 + grp + 24] = o1[3];
        __syncthreads();
        float g = *gamma_p;
        for (int i = tid; i < 64 * 32; i += 256) {
            int d = i >> 5, q = i & 31;
            int gi = (h * HD + d) * HW + q0 + q;
            out[gi] = g * sT[d * 33 + q] * sInv[q] + x[gi];
        }
    }
}

// ---------------------------------------------------------------------------
extern "C" void kernel_launch(void* const* d_in, const int* in_sizes, int n_in,
                              void* d_out, int out_size) {
    const float* x     = (const float*)d_in[0];
    const float* Wq    = (const float*)d_in[1];
    const float* bq    = (const float*)d_in[2];
    const float* Wk    = (const float*)d_in[3];
    const float* bk    = (const float*)d_in[4];
    const float* Wv    = (const float*)d_in[5];
    const float* bv    = (const float*)d_in[6];
    const float* gamma = (const float*)d_in[7];
    float* out = (float*)d_out;

    pad_kernel<<<(C_ * KP + 255) / 256, 256>>>(x);
    gemm_all_kernel<<<312, 128>>>(Wq, bq, Wk, bk, Wv, bv, x);

    const int attn_smem = (1024 + 4608 + 32 * SEW + 32) * 4;  // 146048
    cudaFuncSetAttribute(attn_kernel, cudaFuncAttributeMaxDynamicSharedMemorySize, attn_smem);
    attn_kernel<<<dim3(HW / 32, NH), 256, attn_smem>>>(x, gamma, out);
}

// round 17
// speedup vs baseline: 1.5391x; 1.0316x over previous
#include <cuda_runtime.h>
#include <cuda_bf16.h>
#include <cstdint>

#define C_  512
#define Hh  24
#define Ww  24
#define HW  576
#define NH  8
#define HD  64
#define PW  30
#define PP  900
#define KP  960
#define SEP 484            /* sE PAIR stride (u32): 4 mod 32 -> conflict-free */

typedef unsigned long long ull;

// Scratch (device globals: allocation-free)
__device__ float g_Xp[C_ * KP];   // reflect-padded x
__device__ float g_QT[HW * C_];   // Q transposed: [p][o]
__device__ float g_KT[KP * C_];   // K transposed: [pp][o]
__device__ float g_V [C_ * KP];   // V: [o][pp]

// ---- bf16 helpers ----
__device__ __forceinline__ uint32_t pkbf(float lo, float hi) {
    __nv_bfloat162 h = __floats2bfloat162_rn(lo, hi);
    return *(uint32_t*)&h;
}
__device__ __forceinline__ void mma_bf16(float* c, const uint32_t* a, const uint32_t* b) {
    asm("mma.sync.aligned.m16n8k16.row.col.f32.bf16.bf16.f32 "
        "{%0,%1,%2,%3}, {%4,%5,%6,%7}, {%8,%9}, {%0,%1,%2,%3};"
        : "+f"(c[0]), "+f"(c[1]), "+f"(c[2]), "+f"(c[3])
        : "r"(a[0]), "r"(a[1]), "r"(a[2]), "r"(a[3]), "r"(b[0]), "r"(b[1]));
}

// ---------------------------------------------------------------------------
// Kernel 1: reflect-pad gather (R16 verbatim).
// ---------------------------------------------------------------------------
__global__ void pad_kernel(const float* __restrict__ x) {
    int idx = blockIdx.x * 256 + threadIdx.x;
    if (idx >= C_ * KP) return;
    int c = idx / KP, pp = idx - c * KP;
    float v = 0.f;
    if (pp < PP) {
        int pr = pp / PW, pc = pp - pr * PW;
        int r = pr - 3; r = (r < 0) ? -r : ((r >= Hh) ? 2 * Hh - 2 - r : r);
        int cl = pc - 3; cl = (cl < 0) ? -cl : ((cl >= Ww) ? 2 * Ww - 2 - cl : cl);
        v = x[c * HW + r * Ww + cl];
    }
    g_Xp[idx] = v;
}

// ---------------------------------------------------------------------------
// Kernel 2: three conv1x1 GEMMs via mma.sync BF16 m16n8k16 (R16 verbatim).
// ---------------------------------------------------------------------------
__global__ void __launch_bounds__(128) gemm_all_kernel(
    const float* __restrict__ Wq, const float* __restrict__ bq,
    const float* __restrict__ Wk, const float* __restrict__ bk,
    const float* __restrict__ Wv, const float* __restrict__ bv,
    const float* __restrict__ x)
{
    __shared__ uint32_t smu[4736];
    uint32_t* sA[2] = { smu,        smu + 1280 };   // [o=64][k2], stride 20
    uint32_t* sB[2] = { smu + 2560, smu + 3648 };   // [k2=16][n], stride 68

    int bid = blockIdx.x;
    const float *Wm, *bias, *X; float* Cout; int N, transp, nt, ot;
    if (bid < 72)       { nt = bid % 9;      ot = bid / 9;       Wm = Wq; bias = bq; X = x;    Cout = g_QT; N = HW; transp = 1; }
    else if (bid < 192) { int b = bid - 72;  nt = b % 15; ot = b / 15; Wm = Wk; bias = bk; X = g_Xp; Cout = g_KT; N = KP; transp = 1; }
    else                { int b = bid - 192; nt = b % 15; ot = b / 15; Wm = Wv; bias = bv; X = g_Xp; Cout = g_V;  N = KP; transp = 0; }
    int nB = nt * 64, oB = ot * 64;

    int tid  = threadIdx.x;
    int lane = tid & 31, wid = tid >> 5;
    int warp_m = wid & 1, warp_n = wid >> 1;
    int grp = lane >> 2, qd = lane & 3;

    int arow = tid >> 1, ahalf = tid & 1;
    int bk2  = tid >> 3, bng = (tid & 7) << 3;

    float acc[2][4][4];
#pragma unroll
    for (int i = 0; i < 2; i++)
#pragma unroll
        for (int j = 0; j < 4; j++)
#pragma unroll
            for (int e = 0; e < 4; e++) acc[i][j][e] = 0.f;

    {
        const float4* aS = (const float4*)&Wm[(oB + arow) * C_ + ahalf * 16];
        const float4* b0S = (const float4*)&X[(2 * bk2    ) * N + nB + bng];
        const float4* b1S = (const float4*)&X[(2 * bk2 + 1) * N + nB + bng];
        uint32_t aw[8], bw[8];
#pragma unroll
        for (int g = 0; g < 4; g++) {
            float4 w = aS[g];
            aw[2 * g]     = pkbf(w.x, w.y);
            aw[2 * g + 1] = pkbf(w.z, w.w);
        }
#pragma unroll
        for (int g = 0; g < 2; g++) {
            float4 lo = b0S[g], hi = b1S[g];
            bw[4 * g + 0] = pkbf(lo.x, hi.x);
            bw[4 * g + 1] = pkbf(lo.y, hi.y);
            bw[4 * g + 2] = pkbf(lo.z, hi.z);
            bw[4 * g + 3] = pkbf(lo.w, hi.w);
        }
        *(uint4*)&sA[0][arow * 20 + ahalf * 8]     = *(uint4*)&aw[0];
        *(uint4*)&sA[0][arow * 20 + ahalf * 8 + 4] = *(uint4*)&aw[4];
        *(uint4*)&sB[0][bk2 * 68 + bng]            = *(uint4*)&bw[0];
        *(uint4*)&sB[0][bk2 * 68 + bng + 4]        = *(uint4*)&bw[4];
    }
    __syncthreads();

    int buf = 0;
    for (int cc = 0; cc < C_; cc += 32) {
        bool pf = cc + 32 < C_;
        float4 wreg[4], x0reg[2], x1reg[2];
        if (pf) {
            const float4* aS = (const float4*)&Wm[(oB + arow) * C_ + cc + 32 + ahalf * 16];
            const float4* b0S = (const float4*)&X[(cc + 32 + 2 * bk2    ) * N + nB + bng];
            const float4* b1S = (const float4*)&X[(cc + 32 + 2 * bk2 + 1) * N + nB + bng];
#pragma unroll
            for (int g = 0; g < 4; g++) wreg[g] = aS[g];
            x0reg[0] = b0S[0]; x0reg[1] = b0S[1];
            x1reg[0] = b1S[0]; x1reg[1] = b1S[1];
        }
        const uint32_t* cA = sA[buf];
        const uint32_t* cB = sB[buf];
#pragma unroll
        for (int ks = 0; ks < 2; ks++) {
            int kb = ks << 3;
            uint32_t afr[2][4];
#pragma unroll
            for (int ms = 0; ms < 2; ms++) {
                int base = warp_m * 32 + ms * 16 + grp;
                afr[ms][0] = cA[(base    ) * 20 + kb + qd];
                afr[ms][1] = cA[(base + 8) * 20 + kb + qd];
                afr[ms][2] = cA[(base    ) * 20 + kb + 4 + qd];
                afr[ms][3] = cA[(base + 8) * 20 + kb + 4 + qd];
            }
            uint32_t bfr[4][2];
#pragma unroll
            for (int ns = 0; ns < 4; ns++) {
                int n = warp_n * 32 + ns * 8 + grp;
                bfr[ns][0] = cB[(kb + qd    ) * 68 + n];
                bfr[ns][1] = cB[(kb + 4 + qd) * 68 + n];
            }
#pragma unroll
            for (int ms = 0; ms < 2; ms++)
#pragma unroll
                for (int ns = 0; ns < 4; ns++)
                    mma_bf16(acc[ms][ns], afr[ms], bfr[ns]);
        }
        if (pf) {
            uint32_t* nA = sA[buf ^ 1];
            uint32_t* nBp = sB[buf ^ 1];
            uint32_t aw[8], bw[8];
#pragma unroll
            for (int g = 0; g < 4; g++) {
                aw[2 * g]     = pkbf(wreg[g].x, wreg[g].y);
                aw[2 * g + 1] = pkbf(wreg[g].z, wreg[g].w);
            }
#pragma unroll
            for (int g = 0; g < 2; g++) {
                float4 lo = x0reg[g], hi = x1reg[g];
                bw[4 * g + 0] = pkbf(lo.x, hi.x);
                bw[4 * g + 1] = pkbf(lo.y, hi.y);
                bw[4 * g + 2] = pkbf(lo.z, hi.z);
                bw[4 * g + 3] = pkbf(lo.w, hi.w);
            }
            *(uint4*)&nA[arow * 20 + ahalf * 8]     = *(uint4*)&aw[0];
            *(uint4*)&nA[arow * 20 + ahalf * 8 + 4] = *(uint4*)&aw[4];
            *(uint4*)&nBp[bk2 * 68 + bng]           = *(uint4*)&bw[0];
            *(uint4*)&nBp[bk2 * 68 + bng + 4]       = *(uint4*)&bw[4];
        }
        __syncthreads();
        buf ^= 1;
    }

    if (!transp) {
#pragma unroll
        for (int ms = 0; ms < 2; ms++)
#pragma unroll
            for (int part = 0; part < 2; part++) {
                int row = warp_m * 32 + ms * 16 + grp + part * 8;
                float bv_ = bias[oB + row];
#pragma unroll
                for (int ns = 0; ns < 4; ns++) {
                    float2 val = make_float2(acc[ms][ns][2 * part] + bv_,
                                             acc[ms][ns][2 * part + 1] + bv_);
                    *(float2*)&Cout[(oB + row) * N + nB + warp_n * 32 + ns * 8 + 2 * qd] = val;
                }
            }
    } else {
        float* sT = (float*)smu;
        __syncthreads();
#pragma unroll
        for (int ms = 0; ms < 2; ms++)
#pragma unroll
            for (int part = 0; part < 2; part++) {
                int row = warp_m * 32 + ms * 16 + grp + part * 8;
                float bv_ = bias[oB + row];
#pragma unroll
                for (int ns = 0; ns < 4; ns++) {
                    int n = warp_n * 32 + ns * 8 + 2 * qd;
                    sT[(n    ) * 65 + row] = acc[ms][ns][2 * part] + bv_;
                    sT[(n + 1) * 65 + row] = acc[ms][ns][2 * part + 1] + bv_;
                }
            }
        __syncthreads();
#pragma unroll
        for (int it = 0; it < 32; it++) {
            int idx = it * 128 + tid;
            int n = idx >> 6, o = idx & 63;
            Cout[(nB + n) * C_ + oB + o] = sT[n * 65 + o];
        }
    }
}

// ---------------------------------------------------------------------------
// Kernel 3: fused attention, ALL-BF16 mma + BF16-PAIR sE + max-free softmax.
// Grid (18,8) = 144 CTAs x 256 thr. smem 84.6KB.
// sE: u32[32][484] bf16 pairs (plain pair order; stride 484 -> 4grp+qd banks).
// Softmax: no max pass (E bounded), incremental multiplicity, bf16 P in place.
// ---------------------------------------------------------------------------
__global__ void __launch_bounds__(256) attn_kernel(const float* __restrict__ x,
                            const float* __restrict__ gamma_p,
                            float* __restrict__ out) {
    extern __shared__ float smd[];
    uint32_t* sQf  = (uint32_t*)smd;            // 1024 u32
    uint32_t* sKV0 = sQf + 1024;                // 2304 u32
    uint32_t* sKV1 = sKV0 + 2304;               // 2304 u32
    uint32_t* sEu  = sKV1 + 2304;               // 32*484 = 15488 u32 (bf16 pairs)
    float* sInv    = (float*)(sEu + 32 * SEP);  // 32 floats

    int h   = blockIdx.y;
    int q0  = blockIdx.x * 32;
    int tid = threadIdx.x;
    int w = tid >> 5, lane = tid & 31, grp = lane >> 2, qd = lane & 3;
    int kd = tid >> 2, kg = (tid & 3) << 4;     // staging: row, 16-float group
    uint32_t* sKVb[2] = { sKV0, sKV1 };

    // ---- Stage Q fragments (one-time), bf16 pairs along d ----
    {
        int q = tid >> 3, db = (tid & 7) << 3;
        float4 qa = *(const float4*)&g_QT[(q0 + q) * C_ + h * HD + db];
        float4 qb = *(const float4*)&g_QT[(q0 + q) * C_ + h * HD + db + 4];
        float qv[8] = {qa.x, qa.y, qa.z, qa.w, qb.x, qb.y, qb.z, qb.w};
        int ms = q >> 4, qrow = q & 15;
        int reg = (((db >> 3) & 1) << 1) + (qrow >> 3);
        int base = ((ms * 4 + (db >> 4)) * 32 + (qrow & 7) * 4) * 4 + reg;
#pragma unroll
        for (int j = 0; j < 4; j++)
            sQf[base + j * 4] = pkbf(qv[2 * j], qv[2 * j + 1]);
    }
    // ---- preload K chunk 0: sK[key][36], pairs along d ----
    {
        const float4* src = (const float4*)&g_KT[kd * C_ + h * HD + kg];
        uint32_t pw[8];
#pragma unroll
        for (int j = 0; j < 4; j++) {
            float4 r = src[j];
            pw[2 * j]     = pkbf(r.x, r.y);
            pw[2 * j + 1] = pkbf(r.z, r.w);
        }
        *(uint4*)&sKV0[kd * 36 + (kg >> 1)]     = *(uint4*)&pw[0];
        *(uint4*)&sKV0[kd * 36 + (kg >> 1) + 4] = *(uint4*)&pw[4];
    }
    __syncthreads();

    // ---- Pass 1: E = Q^T K, bf16 k16, E stored as bf16 pairs ----
    for (int kc = 0, c = 0; kc < KP; kc += 64, c++) {
        const uint32_t* cK = sKVb[c & 1];
        bool pf = kc + 64 < KP;
        float4 r0, r1, r2, r3;
        if (pf) {
            const float4* src = (const float4*)&g_KT[(kc + 64 + kd) * C_ + h * HD + kg];
            r0 = src[0]; r1 = src[1]; r2 = src[2]; r3 = src[3];
        }
        float acc0[4] = {0.f, 0.f, 0.f, 0.f};
        float acc1[4] = {0.f, 0.f, 0.f, 0.f};
#pragma unroll
        for (int ks = 0; ks < 4; ks++) {
            uint4 a0 = *(const uint4*)&sQf[((    ks) * 32 + lane) * 4];
            uint4 a1 = *(const uint4*)&sQf[((4 + ks) * 32 + lane) * 4];
            uint32_t bf[2];
            bf[0] = cK[(w * 8 + grp) * 36 + ks * 8 + qd];
            bf[1] = cK[(w * 8 + grp) * 36 + ks * 8 + 4 + qd];
            mma_bf16(acc0, (const uint32_t*)&a0, bf);
            mma_bf16(acc1, (const uint32_t*)&a1, bf);
        }
        {
            int pc0 = (kc >> 1) + w * 4 + qd;    // pair-col index
            sEu[(grp     ) * SEP + pc0] = pkbf(acc0[0], acc0[1]);
            sEu[(grp +  8) * SEP + pc0] = pkbf(acc0[2], acc0[3]);
            sEu[(grp + 16) * SEP + pc0] = pkbf(acc1[0], acc1[1]);
            sEu[(grp + 24) * SEP + pc0] = pkbf(acc1[2], acc1[3]);
        }
        if (pf) {
            uint32_t pw[8];
            pw[0] = pkbf(r0.x, r0.y); pw[1] = pkbf(r0.z, r0.w);
            pw[2] = pkbf(r1.x, r1.y); pw[3] = pkbf(r1.z, r1.w);
            pw[4] = pkbf(r2.x, r2.y); pw[5] = pkbf(r2.z, r2.w);
            pw[6] = pkbf(r3.x, r3.y); pw[7] = pkbf(r3.z, r3.w);
            uint32_t* dst = &sKVb[(c & 1) ^ 1][kd * 36 + (kg >> 1)];
            *(uint4*)&dst[0] = *(uint4*)&pw[0];
            *(uint4*)&dst[4] = *(uint4*)&pw[4];
        }
        __syncthreads();
    }

    // ---- prefetch V chunk 0 ----
    float4 v0r, v1r, v2r, v3r;
    {
        const float4* src = (const float4*)&g_V[(h * HD + kd) * KP + kg];
        v0r = src[0]; v1r = src[1]; v2r = src[2]; v3r = src[3];
    }

    // ---- Max-free weighted softmax on bf16 pairs, in place ----
    {
        int row = tid >> 3, part = tid & 7;      // 8 threads per query row
        uint32_t* Er = &sEu[row * SEP];
        int j0 = part * 60;                      // 60 pairs = 120 cols
        int i = j0 << 1;
        int pr = i / PW, pc = i - pr * PW;       // one constant-divide at entry
        float s = 0.f;
        for (int j = j0; j < j0 + 60; j++) {
            uint32_t u = Er[j];
            __nv_bfloat162 e2 = *(__nv_bfloat162*)&u;
            float e0 = __bfloat162float(e2.x);
            float e1 = __bfloat162float(e2.y);
            int mr0 = max(0, min(pr + 1, min(7, PW - pr)));
            int mc0 = min(pc + 1, min(7, PW - pc));
            float w0 = (float)(mr0 * mc0);
            pc++; if (pc == PW) { pc = 0; pr++; }
            int mr1 = max(0, min(pr + 1, min(7, PW - pr)));
            int mc1 = min(pc + 1, min(7, PW - pc));
            float w1 = (float)(mr1 * mc1);
            pc++; if (pc == PW) { pc = 0; pr++; }
            float p0 = w0 * __expf(e0);
            float p1 = w1 * __expf(e1);
            __nv_bfloat162 h2 = __floats2bfloat162_rn(p0, p1);
            s += __bfloat162float(h2.x) + __bfloat162float(h2.y);
            Er[j] = *(uint32_t*)&h2;
        }
        s += __shfl_xor_sync(~0u, s, 1);
        s += __shfl_xor_sync(~0u, s, 2);
        s += __shfl_xor_sync(~0u, s, 4);
        if (part == 0) sInv[row] = 1.f / s;
    }
    // store V chunk 0: sV[d][36], pairs along key
    {
        uint32_t pw[8];
        pw[0] = pkbf(v0r.x, v0r.y); pw[1] = pkbf(v0r.z, v0r.w);
        pw[2] = pkbf(v1r.x, v1r.y); pw[3] = pkbf(v1r.z, v1r.w);
        pw[4] = pkbf(v2r.x, v2r.y); pw[5] = pkbf(v2r.z, v2r.w);
        pw[6] = pkbf(v3r.x, v3r.y); pw[7] = pkbf(v3r.z, v3r.w);
        uint32_t* dst = &sKV0[kd * 36 + (kg >> 1)];
        *(uint4*)&dst[0] = *(uint4*)&pw[0];
        *(uint4*)&dst[4] = *(uint4*)&pw[4];
    }
    __syncthreads();

    // ---- Pass 2: out = P V, bf16 k16; A-frags = plain pair reads ----
    float o0[4] = {0.f, 0.f, 0.f, 0.f};
    float o1[4] = {0.f, 0.f, 0.f, 0.f};
    for (int kc = 0, c = 0; kc < KP; kc += 64, c++) {
        const uint32_t* cV = sKVb[c & 1];
        bool pf = kc + 64 < KP;
        float4 r0, r1, r2, r3;
        if (pf) {
            const float4* src = (const float4*)&g_V[(h * HD + kd) * KP + kc + 64 + kg];
            r0 = src[0]; r1 = src[1]; r2 = src[2]; r3 = src[3];
        }
#pragma unroll
        for (int ks = 0; ks < 4; ks++) {
            int cb2 = (kc >> 1) + 8 * ks;        // pair base of this k16 step
            uint32_t a0[4], a1[4], bf[2];
            a0[0] = sEu[(grp     ) * SEP + cb2 + qd];
            a0[1] = sEu[(grp +  8) * SEP + cb2 + qd];
            a0[2] = sEu[(grp     ) * SEP + cb2 + 4 + qd];
            a0[3] = sEu[(grp +  8) * SEP + cb2 + 4 + qd];
            a1[0] = sEu[(grp + 16) * SEP + cb2 + qd];
            a1[1] = sEu[(grp + 24) * SEP + cb2 + qd];
            a1[2] = sEu[(grp + 16) * SEP + cb2 + 4 + qd];
            a1[3] = sEu[(grp + 24) * SEP + cb2 + 4 + qd];
            bf[0] = cV[(w * 8 + grp) * 36 + ks * 8 + qd];
            bf[1] = cV[(w * 8 + grp) * 36 + ks * 8 + 4 + qd];
            mma_bf16(o0, a0, bf);
            mma_bf16(o1, a1, bf);
        }
        if (pf) {
            uint32_t pw[8];
            pw[0] = pkbf(r0.x, r0.y); pw[1] = pkbf(r0.z, r0.w);
            pw[2] = pkbf(r1.x, r1.y); pw[3] = pkbf(r1.z, r1.w);
            pw[4] = pkbf(r2.x, r2.y); pw[5] = pkbf(r2.z, r2.w);
            pw[6] = pkbf(r3.x, r3.y); pw[7] = pkbf(r3.z, r3.w);
            uint32_t* dst = &sKVb[(c & 1) ^ 1][kd * 36 + (kg >> 1)];
            *(uint4*)&dst[0] = *(uint4*)&pw[0];
            *(uint4*)&dst[4] = *(uint4*)&pw[4];
        }
        __syncthreads();
    }

    // ---- Epilogue via smem transpose: out = gamma*acc/denom + x ----
    {
        float* sT = (float*)sKV0;                // [d][q] 64 x 33 = 2112 floats
        int dc = w * 8 + 2 * qd;
        sT[(dc    ) * 33 + grp     ] = o0[0];
        sT[(dc + 1) * 33 + grp     ] = o0[1];
        sT[(dc    ) * 33 + grp +  8] = o0[2];
        sT[(dc + 1) * 33 + grp +  8] = o0[3];
        sT[(dc    ) * 33 + grp + 16] = o1[0];
        sT[(dc + 1) * 33 + grp + 16] = o1[1];
        sT[(dc    ) * 33 + grp + 24] = o1[2];
        sT[(dc + 1) * 33 + grp + 24] = o1[3];
        __syncthreads();
        float g = *gamma_p;
        for (int i = tid; i < 64 * 32; i += 256) {
            int d = i >> 5, q = i & 31;
            int gi = (h * HD + d) * HW + q0 + q;
            out[gi] = g * sT[d * 33 + q] * sInv[q] + x[gi];
        }
    }
}

// ---------------------------------------------------------------------------
extern "C" void kernel_launch(void* const* d_in, const int* in_sizes, int n_in,
                              void* d_out, int out_size) {
    const float* x     = (const float*)d_in[0];
    const float* Wq    = (const float*)d_in[1];
    const float* bq    = (const float*)d_in[2];
    const float* Wk    = (const float*)d_in[3];
    const float* bk    = (const float*)d_in[4];
    const float* Wv    = (const float*)d_in[5];
    const float* bv    = (const float*)d_in[6];
    const float* gamma = (const float*)d_in[7];
    float* out = (float*)d_out;

    pad_kernel<<<(C_ * KP + 255) / 256, 256>>>(x);
    gemm_all_kernel<<<312, 128>>>(Wq, bq, Wk, bk, Wv, bv, x);

    const int attn_smem = (1024 + 2 * 2304 + 32 * SEP + 32) * 4;  // 84608
    cudaFuncSetAttribute(attn_kernel, cudaFuncAttributeMaxDynamicSharedMemorySize, attn_smem);
    attn_kernel<<<dim3(HW / 32, NH), 256, attn_smem>>>(x, gamma, out);
}